// round 13
// baseline (speedup 1.0000x reference)
#include <cuda_runtime.h>
#include <cuda_fp16.h>
#include <cstdint>

#define NTOK 8192
#define DIN  512
#define DHEAD 256
#define NSPLIT 2
#define BM 128
#define BN 64
#define JBLOCKS (NTOK / NSPLIT / BN)   // 64

// ---------------- scratch ----------------
// Pre-swizzled B images: [mat][n0t(2)][kbt(16)] blocks of 8KB, exact smem layout.
__device__ __half2 g_Wb[3 * 2 * 16 * 128 * 16];
__device__ __half  g_Qh[NTOK * DHEAD];        // fp16, pre-scaled by log2e/16
__device__ __half  g_Kh[NTOK * DHEAD];        // fp16
__device__ __half  g_Vt[DHEAD * NTOK];        // V transposed [d][tok], fp16
__device__ float   g_Op[NSPLIT][NTOK][DHEAD];
__device__ float   g_ls[NSPLIT][NTOK];
__device__ int     g_done[NTOK / BM];         // zero-init; reset by combiner each run

// ---------------- helpers ----------------
__device__ __forceinline__ uint32_t smem_u32(const void* p) {
    uint32_t a;
    asm("{ .reg .u64 t; cvta.to.shared.u64 t, %1; cvt.u32.u64 %0, t; }" : "=r"(a) : "l"(p));
    return a;
}
__device__ __forceinline__ void cp16(uint32_t dst, const void* src) {
    asm volatile("cp.async.cg.shared.global [%0], [%1], 16;" :: "r"(dst), "l"(src));
}
#define CP_COMMIT() asm volatile("cp.async.commit_group;" ::: "memory")
#define CP_WAIT(n)  asm volatile("cp.async.wait_group %0;" :: "n"(n) : "memory")

__device__ __forceinline__ void ldsm4(unsigned& r0, unsigned& r1, unsigned& r2, unsigned& r3,
                                      uint32_t a) {
    asm volatile("ldmatrix.sync.aligned.m8n8.x4.shared.b16 {%0,%1,%2,%3}, [%4];"
                 : "=r"(r0), "=r"(r1), "=r"(r2), "=r"(r3) : "r"(a));
}

__device__ __forceinline__ void mma_f16(float& c0, float& c1, float& c2, float& c3,
                                        unsigned a0, unsigned a1, unsigned a2, unsigned a3,
                                        unsigned b0, unsigned b1) {
    asm volatile(
        "mma.sync.aligned.m16n8k16.row.col.f32.f16.f16.f32 "
        "{%0,%1,%2,%3}, {%4,%5,%6,%7}, {%8,%9}, {%0,%1,%2,%3};"
        : "+f"(c0), "+f"(c1), "+f"(c2), "+f"(c3)
        : "r"(a0), "r"(a1), "r"(a2), "r"(a3), "r"(b0), "r"(b1));
}

__device__ __forceinline__ float ex2f(float x) {
    float r; asm("ex2.approx.f32 %0, %1;" : "=f"(r) : "f"(x)); return r;
}

__device__ __forceinline__ unsigned pack_hi(float a, float b) {
    __half2 h = __halves2half2(__float2half_rn(a), __float2half_rn(b));
    return *(unsigned*)&h;
}
__device__ __forceinline__ unsigned pack_lo(float a, float b) {
    float ra = a - __half2float(__float2half_rn(a));
    float rb = b - __half2float(__float2half_rn(b));
    __half2 h = __halves2half2(__float2half_rn(ra), __float2half_rn(rb));
    return *(unsigned*)&h;
}

// ---------------- kernel 0: build pre-swizzled B images ----------------
// Block layout (8KB, matches proj's Bs buffer exactly):
//   half2 index = n*16 + pc*4 + e ; pc = lc ^ ((n>>1)&3) ;
//   value = (W[2*k2g][n0t*128+n], W[2*k2g+1][...]) with k2g = kbt*16 + lc*4 + e.
__global__ __launch_bounds__(256) void prep_wb(const float* __restrict__ Wq,
                                               const float* __restrict__ Wk,
                                               const float* __restrict__ Wv) {
    const int idx = blockIdx.x * 256 + threadIdx.x;   // over 196608 half2
    if (idx >= 3 * 2 * 16 * 128 * 16) return;
    const int e = idx & 3;
    const int pc = (idx >> 2) & 3;
    const int n = (idx >> 4) & 127;
    const int kbt = (idx >> 11) & 15;
    const int n0t = (idx >> 15) & 1;
    const int mat = idx >> 16;
    const int lc = pc ^ ((n >> 1) & 3);
    const int k2g = kbt * 16 + lc * 4 + e;
    const int col = n0t * 128 + n;
    const float* __restrict__ W = (mat == 0) ? Wq : ((mat == 1) ? Wk : Wv);
    g_Wb[idx] = __halves2half2(__float2half_rn(W[(size_t)(2 * k2g) * DHEAD + col]),
                               __float2half_rn(W[(size_t)(2 * k2g + 1) * DHEAD + col]));
}

// ---------------- kernel 1: QKV projection — BM=64, cp.async B, pipelined A ----------------
__global__ __launch_bounds__(256) void proj_kernel(const float* __restrict__ feat) {
    __shared__ __align__(16) __half2 As[2][64][16];    // [hi/lo][row][chunk^((row>>1)&3)]
    __shared__ __align__(16) __half2 Bs[2][128][16];   // double-buffered B image

    const int tid = threadIdx.x;
    const int w = tid >> 5, lane = tid & 31, g = lane >> 2, t = lane & 3;
    const int wm = w >> 2;        // 0..1
    const int wn = w & 3;         // 0..3
    const int m0 = blockIdx.x * 64;
    const int n0 = blockIdx.y * 128;
    const int mat = blockIdx.z;
    const uint32_t sbB = smem_u32(&Bs[0][0][0]);
    const __half2* __restrict__ WbBase = &g_Wb[(size_t)((mat * 2 + blockIdx.y) * 16) * 2048];

    const int ar = tid >> 2;
    const int ac = tid & 3;
    const int aq = (ar >> 1) & 3;

    // prologue: B_0 via cp.async (coalesced 32B/thread), A_0 via LDG
    cp16(sbB + (uint32_t)tid * 32u, (const char*)WbBase + tid * 32);
    cp16(sbB + (uint32_t)tid * 32u + 16u, (const char*)WbBase + tid * 32 + 16);
    CP_COMMIT();

    float4 aR[2];
    {
        const float* ap = &feat[(size_t)(m0 + ar) * DIN + ac * 8];
        aR[0] = *(const float4*)(ap);
        aR[1] = *(const float4*)(ap + 4);
    }

    float acc[2][4][4];
#pragma unroll
    for (int mt = 0; mt < 2; mt++)
#pragma unroll
        for (int nt = 0; nt < 4; nt++)
#pragma unroll
            for (int q = 0; q < 4; q++) acc[mt][nt][q] = 0.f;

    for (int it = 0; it < 16; it++) {
        // store A_it (convert hi/lo)
        {
            uint4 hq, lq;
            hq.x = pack_hi(aR[0].x, aR[0].y); hq.y = pack_hi(aR[0].z, aR[0].w);
            hq.z = pack_hi(aR[1].x, aR[1].y); hq.w = pack_hi(aR[1].z, aR[1].w);
            lq.x = pack_lo(aR[0].x, aR[0].y); lq.y = pack_lo(aR[0].z, aR[0].w);
            lq.z = pack_lo(aR[1].x, aR[1].y); lq.w = pack_lo(aR[1].z, aR[1].w);
            *(uint4*)&As[0][ar][(ac ^ aq) << 2] = hq;
            *(uint4*)&As[1][ar][(ac ^ aq) << 2] = lq;
        }
        // issue B_{it+1}, then complete B_it
        if (it + 1 < 16) {
            uint32_t d = sbB + (uint32_t)(((it + 1) & 1) * 8192) + (uint32_t)tid * 32u;
            const char* s = (const char*)WbBase + (it + 1) * 8192 + tid * 32;
            cp16(d, s);
            cp16(d + 16u, s + 16);
            CP_COMMIT();
            CP_WAIT(1);
        } else {
            CP_WAIT(0);
        }
        __syncthreads();

        // prefetch A_{it+1}
        if (it + 1 < 16) {
            const int kb = (it + 1) << 5;
            const float* ap = &feat[(size_t)(m0 + ar) * DIN + kb + ac * 8];
            aR[0] = *(const float4*)(ap);
            aR[1] = *(const float4*)(ap + 4);
        }

        const int buf = it & 1;
#pragma unroll
        for (int ks = 0; ks < 2; ks++) {
            unsigned bfr[4][2];
#pragma unroll
            for (int nt = 0; nt < 4; nt++) {
                int n = 32 * wn + 8 * nt + g;
                int qn = (n >> 1) & 3;
                bfr[nt][0] = *(const unsigned*)&Bs[buf][n][(((2 * ks    ) ^ qn) << 2) + t];
                bfr[nt][1] = *(const unsigned*)&Bs[buf][n][(((2 * ks + 1) ^ qn) << 2) + t];
            }
#pragma unroll
            for (int sp = 0; sp < 2; sp++) {
#pragma unroll
                for (int mt = 0; mt < 2; mt++) {
                    int r = 32 * wm + 16 * mt + g;
                    int qr = (r >> 1) & 3;
                    unsigned a0 = *(const unsigned*)&As[sp][r    ][(((2 * ks    ) ^ qr) << 2) + t];
                    unsigned a1 = *(const unsigned*)&As[sp][r + 8][(((2 * ks    ) ^ qr) << 2) + t];
                    unsigned a2 = *(const unsigned*)&As[sp][r    ][(((2 * ks + 1) ^ qr) << 2) + t];
                    unsigned a3 = *(const unsigned*)&As[sp][r + 8][(((2 * ks + 1) ^ qr) << 2) + t];
#pragma unroll
                    for (int nt = 0; nt < 4; nt++)
                        mma_f16(acc[mt][nt][0], acc[mt][nt][1], acc[mt][nt][2], acc[mt][nt][3],
                                a0, a1, a2, a3, bfr[nt][0], bfr[nt][1]);
                }
            }
        }
        __syncthreads();
    }

    // Q scale folds 1/sqrt(256) AND log2(e).
    const float scale = (mat == 0) ? 0.09014020181552054f : 1.0f;
#pragma unroll
    for (int mt = 0; mt < 2; mt++) {
        int r = m0 + 32 * wm + 16 * mt + g;
#pragma unroll
        for (int nt = 0; nt < 4; nt++) {
            int col = n0 + 32 * wn + 8 * nt + 2 * t;
            __half h00 = __float2half_rn(acc[mt][nt][0] * scale);
            __half h01 = __float2half_rn(acc[mt][nt][1] * scale);
            __half h10 = __float2half_rn(acc[mt][nt][2] * scale);
            __half h11 = __float2half_rn(acc[mt][nt][3] * scale);
            if (mat == 2) {
                g_Vt[(size_t)col * NTOK + r] = h00;
                g_Vt[(size_t)(col + 1) * NTOK + r] = h01;
                g_Vt[(size_t)col * NTOK + r + 8] = h10;
                g_Vt[(size_t)(col + 1) * NTOK + r + 8] = h11;
            } else {
                __half* dst = (mat == 0) ? g_Qh : g_Kh;
                *(__half2*)&dst[(size_t)r * DHEAD + col] = __halves2half2(h00, h01);
                *(__half2*)&dst[(size_t)(r + 8) * DHEAD + col] = __halves2half2(h10, h11);
            }
        }
    }
}

// ---------------- kernel 2: fp16 attention + fused combine ----------------
#define SMO_Q   0u
#define SMO_K0  65536u
#define SMO_K1  98304u
#define SMO_V   131072u
#define SMO_C   163840u
#define SMO_P   196608u
#define SMO_L   215040u
#define SMEM_DYN (215040u + 1024u)

__global__ __launch_bounds__(256, 1) void attn_kernel(const float* __restrict__ cnt,
                                                      float* __restrict__ out) {
    extern __shared__ char sm[];
    const uint32_t sb = smem_u32(sm);

    const int tid = threadIdx.x, w = tid >> 5, lane = tid & 31;
    const int g = lane >> 2, t = lane & 3;
    const int wm = w & 3, wh = w >> 2;
    const int m0 = blockIdx.x * BM;
    const int sp = blockIdx.y;
    const int jb0 = sp * (NTOK / NSPLIT);

    const int lr = lane & 7;
    const int lm = (lane >> 3) & 1;
    const int lh = lane >> 4;

    const int ar0 = 32 * wm + lr + 8 * lm;
    const uint32_t qb0 = sb + SMO_Q + (uint32_t)ar0 * 512u;
    const uint32_t qb1 = qb0 + 16u * 512u;
    const uint32_t pb0 = sb + SMO_P + (uint32_t)ar0 * 144u;
    const uint32_t pb1 = pb0 + 16u * 144u;
    const int bnr = lr + 8 * lh;
    const uint32_t kroff = (uint32_t)(32 * wh + bnr) * 512u;
    const uint32_t vb = sb + SMO_V + (uint32_t)(128 * wh + bnr) * 128u;

    const uint32_t cw = sb + SMO_C + (uint32_t)w * 4096u;
    const float* crow = &cnt[(size_t)(m0 + 32 * wm) * NTOK + 32 * wh];
    const int crr = lane >> 3;
    const int cf4 = lane & 7;

#pragma unroll
    for (int i = 0; i < 16; i++) {
        int e = tid + 256 * i;
        int r = e >> 5, blk = e & 31;
        uint32_t d = sb + SMO_Q + (uint32_t)r * 512u + (uint32_t)((blk ^ (r & 7)) << 4);
        cp16(d, &g_Qh[(size_t)(m0 + r) * DHEAD + 8 * blk]);
    }
#pragma unroll
    for (int i = 0; i < 8; i++) {
        int e = tid + 256 * i;
        int r = e >> 5, blk = e & 31;
        uint32_t d = sb + SMO_K0 + (uint32_t)r * 512u + (uint32_t)((blk ^ (r & 7)) << 4);
        cp16(d, &g_Kh[(size_t)(jb0 + r) * DHEAD + 8 * blk]);
    }
    CP_COMMIT();

    float O[2][16][4];
#pragma unroll
    for (int mt = 0; mt < 2; mt++)
#pragma unroll
        for (int nt = 0; nt < 16; nt++)
#pragma unroll
            for (int q = 0; q < 4; q++) O[mt][nt][q] = 0.f;
    float lA[2] = {0.f, 0.f}, lB[2] = {0.f, 0.f};

    for (int j = 0; j < JBLOCKS; j++) {
        const int jb = jb0 + j * BN;

        CP_WAIT(0);        // only K_j's group outstanding here
        __syncthreads();   // b1: K_j visible; all buffers free

        // issue V_j + warp-private C_j (group G_V)
#pragma unroll
        for (int i = 0; i < 8; i++) {
            int e = tid + 256 * i;
            int dd = e >> 3, blk = e & 7;
            uint32_t d = sb + SMO_V + (uint32_t)dd * 128u + (uint32_t)((blk ^ (dd & 7)) << 4);
            cp16(d, &g_Vt[(size_t)dd * NTOK + jb + 8 * blk]);
        }
#pragma unroll
        for (int i = 0; i < 8; i++) {
            int row = crr + 4 * i;
            uint32_t d = cw + (uint32_t)row * 128u + (uint32_t)((cf4 ^ (row & 7)) << 4);
            cp16(d, crow + (size_t)row * NTOK + jb + 4 * cf4);
        }
        CP_COMMIT();

        // issue K_{j+1} (group G_K)
        if (j + 1 < JBLOCKS) {
            uint32_t kb = ((j + 1) & 1) ? SMO_K1 : SMO_K0;
#pragma unroll
            for (int i = 0; i < 8; i++) {
                int e = tid + 256 * i;
                int r = e >> 5, blk = e & 31;
                uint32_t d = sb + kb + (uint32_t)r * 512u + (uint32_t)((blk ^ (r & 7)) << 4);
                cp16(d, &g_Kh[(size_t)(jb + BN + r) * DHEAD + 8 * blk]);
            }
        }
        CP_COMMIT();

        // QK_j
        const uint32_t kbuf = sb + ((j & 1) ? SMO_K1 : SMO_K0) + kroff;
        float S[2][4][4];
#pragma unroll
        for (int mt = 0; mt < 2; mt++)
#pragma unroll
            for (int nt = 0; nt < 4; nt++)
#pragma unroll
                for (int q = 0; q < 4; q++) S[mt][nt][q] = 0.f;

#pragma unroll
        for (int s = 0; s < 16; s++) {
            const uint32_t xa = (uint32_t)(((2 * s + lh) ^ lr) << 4);
            const uint32_t xb = (uint32_t)(((2 * s + lm) ^ lr) << 4);
            unsigned a0[4], a1[4], b0[4], b1[4];
            ldsm4(a0[0], a0[1], a0[2], a0[3], qb0 + xa);
            ldsm4(a1[0], a1[1], a1[2], a1[3], qb1 + xa);
            ldsm4(b0[0], b0[1], b0[2], b0[3], kbuf + xb);
            ldsm4(b1[0], b1[1], b1[2], b1[3], kbuf + 16u * 512u + xb);
            mma_f16(S[0][0][0], S[0][0][1], S[0][0][2], S[0][0][3], a0[0], a0[1], a0[2], a0[3], b0[0], b0[1]);
            mma_f16(S[0][1][0], S[0][1][1], S[0][1][2], S[0][1][3], a0[0], a0[1], a0[2], a0[3], b0[2], b0[3]);
            mma_f16(S[0][2][0], S[0][2][1], S[0][2][2], S[0][2][3], a0[0], a0[1], a0[2], a0[3], b1[0], b1[1]);
            mma_f16(S[0][3][0], S[0][3][1], S[0][3][2], S[0][3][3], a0[0], a0[1], a0[2], a0[3], b1[2], b1[3]);
            mma_f16(S[1][0][0], S[1][0][1], S[1][0][2], S[1][0][3], a1[0], a1[1], a1[2], a1[3], b0[0], b0[1]);
            mma_f16(S[1][1][0], S[1][1][1], S[1][1][2], S[1][1][3], a1[0], a1[1], a1[2], a1[3], b0[2], b0[3]);
            mma_f16(S[1][2][0], S[1][2][1], S[1][2][2], S[1][2][3], a1[0], a1[1], a1[2], a1[3], b1[0], b1[1]);
            mma_f16(S[1][3][0], S[1][3][1], S[1][3][2], S[1][3][3], a1[0], a1[1], a1[2], a1[3], b1[2], b1[3]);
        }

        // epilogue, ungated
        CP_WAIT(1);
        __syncwarp();
        const char* Cw = sm + SMO_C + w * 4096;
        char* Ps = sm + SMO_P;
#pragma unroll
        for (int mt = 0; mt < 2; mt++) {
            int lrA = g + 16 * mt, lrB = lrA + 8;
            int rA = 32 * wm + lrA, rB = 32 * wm + lrB;
#pragma unroll
            for (int nt = 0; nt < 4; nt++) {
                int co = (((2 * nt + (t >> 1)) ^ g) << 4) + ((t & 1) << 3);
                float2 cA = *(const float2*)(Cw + lrA * 128 + co);
                float2 cB = *(const float2*)(Cw + lrB * 128 + co);
                float p0 = ex2f(S[mt][nt][0]) * cA.x;
                float p1 = ex2f(S[mt][nt][1]) * cA.y;
                float p2 = ex2f(S[mt][nt][2]) * cB.x;
                float p3 = ex2f(S[mt][nt][3]) * cB.y;
                lA[mt] += p0 + p1;          // per-thread partial; reduced once at end
                lB[mt] += p2 + p3;
                int q = (16 * wh + 4 * nt + t) << 2;
                *(__half2*)(Ps + rA * 144 + q) = __halves2half2(__float2half_rn(p0), __float2half_rn(p1));
                *(__half2*)(Ps + rB * 144 + q) = __halves2half2(__float2half_rn(p2), __float2half_rn(p3));
            }
        }
        __syncthreads();   // b2: P + V visible

        // AV_j
#pragma unroll
        for (int s = 0; s < 4; s++) {
            const uint32_t xp = (uint32_t)((2 * s + lh) << 4);
            const uint32_t xv = (uint32_t)(((2 * s + lm) ^ lr) << 4);
            unsigned pa0[4], pa1[4];
            ldsm4(pa0[0], pa0[1], pa0[2], pa0[3], pb0 + xp);
            ldsm4(pa1[0], pa1[1], pa1[2], pa1[3], pb1 + xp);
#pragma unroll
            for (int p = 0; p < 8; p++) {
                unsigned vv[4];
                ldsm4(vv[0], vv[1], vv[2], vv[3], vb + (uint32_t)p * 2048u + xv);
                mma_f16(O[0][2 * p][0], O[0][2 * p][1], O[0][2 * p][2], O[0][2 * p][3],
                        pa0[0], pa0[1], pa0[2], pa0[3], vv[0], vv[1]);
                mma_f16(O[0][2 * p + 1][0], O[0][2 * p + 1][1], O[0][2 * p + 1][2], O[0][2 * p + 1][3],
                        pa0[0], pa0[1], pa0[2], pa0[3], vv[2], vv[3]);
                mma_f16(O[1][2 * p][0], O[1][2 * p][1], O[1][2 * p][2], O[1][2 * p][3],
                        pa1[0], pa1[1], pa1[2], pa1[3], vv[0], vv[1]);
                mma_f16(O[1][2 * p + 1][0], O[1][2 * p + 1][1], O[1][2 * p + 1][2], O[1][2 * p + 1][3],
                        pa1[0], pa1[1], pa1[2], pa1[3], vv[2], vv[3]);
            }
        }
    }

    // ---- final l reduction (once) ----
#pragma unroll
    for (int mt = 0; mt < 2; mt++) {
        lA[mt] += __shfl_xor_sync(0xffffffffu, lA[mt], 1);
        lA[mt] += __shfl_xor_sync(0xffffffffu, lA[mt], 2);
        lB[mt] += __shfl_xor_sync(0xffffffffu, lB[mt], 1);
        lB[mt] += __shfl_xor_sync(0xffffffffu, lB[mt], 2);
    }
    const int rA0 = 32 * wm + g, rB0 = rA0 + 8;
    float* Lr = (float*)(sm + SMO_L);
    if (t == 0) {
#pragma unroll
        for (int mt = 0; mt < 2; mt++) {
            Lr[wh * 128 + rA0 + 16 * mt] = lA[mt];
            Lr[wh * 128 + rB0 + 16 * mt] = lB[mt];
        }
    }
    __syncthreads();
    if (tid < 128) Lr[tid] = Lr[tid] + Lr[128 + tid];   // full row l
    __syncthreads();

    // ---- write partials ----
    if (tid < 128) g_ls[sp][m0 + tid] = Lr[tid];
#pragma unroll
    for (int mt = 0; mt < 2; mt++) {
        int rA = m0 + rA0 + 16 * mt, rB = m0 + rB0 + 16 * mt;
#pragma unroll
        for (int nt = 0; nt < 16; nt++) {
            int col = 128 * wh + 8 * nt + 2 * t;
            *(float2*)&g_Op[sp][rA][col] = make_float2(O[mt][nt][0], O[mt][nt][1]);
            *(float2*)&g_Op[sp][rB][col] = make_float2(O[mt][nt][2], O[mt][nt][3]);
        }
    }
    __threadfence();

    __shared__ int s_last;
    if (tid == 0) s_last = atomicAdd(&g_done[blockIdx.x], 1);
    __syncthreads();

    // ---- fused combine: second finisher merges reg-O with partner partials ----
    if (s_last == 1) {
        const int osp = 1 - sp;
        float invA[2], invB[2];
#pragma unroll
        for (int mt = 0; mt < 2; mt++) {
            invA[mt] = 1.0f / (Lr[rA0 + 16 * mt] + g_ls[osp][m0 + rA0 + 16 * mt]);
            invB[mt] = 1.0f / (Lr[rB0 + 16 * mt] + g_ls[osp][m0 + rB0 + 16 * mt]);
        }
#pragma unroll
        for (int mt = 0; mt < 2; mt++) {
            int rA = m0 + rA0 + 16 * mt, rB = m0 + rB0 + 16 * mt;
#pragma unroll
            for (int nt = 0; nt < 16; nt++) {
                int col = 128 * wh + 8 * nt + 2 * t;
                float2 oa = *(const float2*)&g_Op[osp][rA][col];
                float2 ob = *(const float2*)&g_Op[osp][rB][col];
                float r0 = (O[mt][nt][0] + oa.x) * invA[mt];
                float r1 = (O[mt][nt][1] + oa.y) * invA[mt];
                float r2 = (O[mt][nt][2] + ob.x) * invB[mt];
                float r3 = (O[mt][nt][3] + ob.y) * invB[mt];
                float2 w0, w1;
                w0.x = (r0 > 0.f) ? r0 : expm1f(r0);
                w0.y = (r1 > 0.f) ? r1 : expm1f(r1);
                w1.x = (r2 > 0.f) ? r2 : expm1f(r2);
                w1.y = (r3 > 0.f) ? r3 : expm1f(r3);
                *(float2*)&out[(size_t)rA * DHEAD + col] = w0;
                *(float2*)&out[(size_t)rB * DHEAD + col] = w1;
            }
        }
        if (tid == 0) g_done[blockIdx.x] = 0;   // reset for next graph replay
    }
}

// ---------------- launch ----------------
extern "C" void kernel_launch(void* const* d_in, const int* in_sizes, int n_in,
                              void* d_out, int out_size) {
    (void)in_sizes; (void)n_in; (void)out_size;
    const float* feat = (const float*)d_in[0];
    const float* cnt = (const float*)d_in[1];
    const float* Wq = (const float*)d_in[2];
    const float* Wk = (const float*)d_in[3];
    const float* Wv = (const float*)d_in[4];

    prep_wb<<<(3 * 2 * 16 * 128 * 16 + 255) / 256, 256>>>(Wq, Wk, Wv);

    proj_kernel<<<dim3(NTOK / 64, DHEAD / 128, 3), 256>>>(feat);

    cudaFuncSetAttribute(attn_kernel, cudaFuncAttributeMaxDynamicSharedMemorySize, (int)SMEM_DYN);
    attn_kernel<<<dim3(NTOK / BM, NSPLIT), 256, SMEM_DYN>>>(cnt, (float*)d_out);
}

// round 14
// speedup vs baseline: 1.1932x; 1.1932x over previous
#include <cuda_runtime.h>
#include <cuda_fp16.h>
#include <cstdint>

#define NTOK 8192
#define DIN  512
#define DHEAD 256
#define NSPLIT 2
#define BM 128
#define BN 64
#define JBLOCKS (NTOK / NSPLIT / BN)   // 64

// ---------------- scratch ----------------
__device__ __half2 g_Wp[3 * (DIN / 2) * DHEAD];  // W packed as k-pairs, fp16
__device__ __half  g_Qh[NTOK * DHEAD];        // fp16, pre-scaled by log2e/16
__device__ __half  g_Kh[NTOK * DHEAD];        // fp16
__device__ __half  g_Vt[DHEAD * NTOK];        // V transposed [d][tok], fp16
__device__ float   g_Op[NSPLIT][NTOK][DHEAD];
__device__ float   g_ls[NSPLIT][NTOK];

// ---------------- helpers ----------------
__device__ __forceinline__ uint32_t smem_u32(const void* p) {
    uint32_t a;
    asm("{ .reg .u64 t; cvta.to.shared.u64 t, %1; cvt.u32.u64 %0, t; }" : "=r"(a) : "l"(p));
    return a;
}
__device__ __forceinline__ void cp16(uint32_t dst, const void* src) {
    asm volatile("cp.async.cg.shared.global [%0], [%1], 16;" :: "r"(dst), "l"(src));
}
#define CP_COMMIT() asm volatile("cp.async.commit_group;" ::: "memory")
#define CP_WAIT(n)  asm volatile("cp.async.wait_group %0;" :: "n"(n) : "memory")

__device__ __forceinline__ void ldsm4(unsigned& r0, unsigned& r1, unsigned& r2, unsigned& r3,
                                      uint32_t a) {
    asm volatile("ldmatrix.sync.aligned.m8n8.x4.shared.b16 {%0,%1,%2,%3}, [%4];"
                 : "=r"(r0), "=r"(r1), "=r"(r2), "=r"(r3) : "r"(a));
}

__device__ __forceinline__ void mma_f16(float& c0, float& c1, float& c2, float& c3,
                                        unsigned a0, unsigned a1, unsigned a2, unsigned a3,
                                        unsigned b0, unsigned b1) {
    asm volatile(
        "mma.sync.aligned.m16n8k16.row.col.f32.f16.f16.f32 "
        "{%0,%1,%2,%3}, {%4,%5,%6,%7}, {%8,%9}, {%0,%1,%2,%3};"
        : "+f"(c0), "+f"(c1), "+f"(c2), "+f"(c3)
        : "r"(a0), "r"(a1), "r"(a2), "r"(a3), "r"(b0), "r"(b1));
}

__device__ __forceinline__ float ex2f(float x) {
    float r; asm("ex2.approx.f32 %0, %1;" : "=f"(r) : "f"(x)); return r;
}

__device__ __forceinline__ unsigned pack_hi(float a, float b) {
    __half2 h = __halves2half2(__float2half_rn(a), __float2half_rn(b));
    return *(unsigned*)&h;
}
__device__ __forceinline__ unsigned pack_lo(float a, float b) {
    float ra = a - __half2float(__float2half_rn(a));
    float rb = b - __half2float(__float2half_rn(b));
    __half2 h = __halves2half2(__float2half_rn(ra), __float2half_rn(rb));
    return *(unsigned*)&h;
}

// ---------------- kernel 0: pack W (1.5 MB one-time) ----------------
__global__ __launch_bounds__(256) void prep_w(const float* __restrict__ Wq,
                                              const float* __restrict__ Wk,
                                              const float* __restrict__ Wv) {
    const int j = blockIdx.x * 256 + threadIdx.x;
    const int WSZ = (DIN / 2) * DHEAD;
    if (j < 3 * WSZ) {
        int mat = j / WSZ;
        int r = j - mat * WSZ;
        int k2 = r / DHEAD, n = r % DHEAD;
        const float* __restrict__ W = (mat == 0) ? Wq : ((mat == 1) ? Wk : Wv);
        g_Wp[j] = __halves2half2(__float2half_rn(W[(size_t)(2 * k2) * DHEAD + n]),
                                 __float2half_rn(W[(size_t)(2 * k2 + 1) * DHEAD + n]));
    }
}

// ---------------- kernel 1: QKV projection — BM=64, BN=128, 32x32 warp tiles ----------------
__global__ __launch_bounds__(256) void proj_kernel(const float* __restrict__ feat) {
    __shared__ __align__(16) __half2 As[2][64][16];
    __shared__ __align__(16) __half2 Bs[128][16];

    const int tid = threadIdx.x;
    const int w = tid >> 5, lane = tid & 31, g = lane >> 2, t = lane & 3;
    const int wm = w >> 2;
    const int wn = w & 3;
    const int m0 = blockIdx.x * 64;
    const int n0 = blockIdx.y * 128;
    const int mat = blockIdx.z;
    const __half2* __restrict__ Wp = &g_Wp[mat * (DIN / 2) * DHEAD];

    const int ar = tid >> 2;
    const int ac = tid & 3;
    const int aq = (ar >> 1) & 3;
    const int bn = tid & 127;
    const int bcb = (tid >> 7) << 1;
    const int bq = (bn >> 1) & 3;

    float4 aR[2];
    unsigned bR[8];
    {
        const float* ap = &feat[(size_t)(m0 + ar) * DIN + ac * 8];
        aR[0] = *(const float4*)(ap);
        aR[1] = *(const float4*)(ap + 4);
        const __half2* bp = &Wp[(size_t)(bcb * 4) * DHEAD + n0 + bn];
#pragma unroll
        for (int jj = 0; jj < 8; jj++) bR[jj] = *(const unsigned*)&bp[(size_t)jj * DHEAD];
    }

    float acc[2][4][4];
#pragma unroll
    for (int mt = 0; mt < 2; mt++)
#pragma unroll
        for (int nt = 0; nt < 4; nt++)
#pragma unroll
            for (int q = 0; q < 4; q++) acc[mt][nt][q] = 0.f;

    for (int it = 0; it < 16; it++) {
        {
            uint4 hq, lq;
            hq.x = pack_hi(aR[0].x, aR[0].y); hq.y = pack_hi(aR[0].z, aR[0].w);
            hq.z = pack_hi(aR[1].x, aR[1].y); hq.w = pack_hi(aR[1].z, aR[1].w);
            lq.x = pack_lo(aR[0].x, aR[0].y); lq.y = pack_lo(aR[0].z, aR[0].w);
            lq.z = pack_lo(aR[1].x, aR[1].y); lq.w = pack_lo(aR[1].z, aR[1].w);
            *(uint4*)&As[0][ar][(ac ^ aq) << 2] = hq;
            *(uint4*)&As[1][ar][(ac ^ aq) << 2] = lq;
            uint4 bq0, bq1;
            bq0.x = bR[0]; bq0.y = bR[1]; bq0.z = bR[2]; bq0.w = bR[3];
            bq1.x = bR[4]; bq1.y = bR[5]; bq1.z = bR[6]; bq1.w = bR[7];
            *(uint4*)&Bs[bn][((bcb    ) ^ bq) << 2] = bq0;
            *(uint4*)&Bs[bn][((bcb + 1) ^ bq) << 2] = bq1;
        }
        __syncthreads();

        if (it + 1 < 16) {
            const int kb = (it + 1) << 5;
            const float* ap = &feat[(size_t)(m0 + ar) * DIN + kb + ac * 8];
            aR[0] = *(const float4*)(ap);
            aR[1] = *(const float4*)(ap + 4);
            const __half2* bp = &Wp[(size_t)(kb / 2 + bcb * 4) * DHEAD + n0 + bn];
#pragma unroll
            for (int jj = 0; jj < 8; jj++) bR[jj] = *(const unsigned*)&bp[(size_t)jj * DHEAD];
        }

#pragma unroll
        for (int ks = 0; ks < 2; ks++) {
            unsigned bfr[4][2];
#pragma unroll
            for (int nt = 0; nt < 4; nt++) {
                int n = 32 * wn + 8 * nt + g;
                int qn = (n >> 1) & 3;
                bfr[nt][0] = *(const unsigned*)&Bs[n][(((2 * ks    ) ^ qn) << 2) + t];
                bfr[nt][1] = *(const unsigned*)&Bs[n][(((2 * ks + 1) ^ qn) << 2) + t];
            }
#pragma unroll
            for (int sp = 0; sp < 2; sp++) {
#pragma unroll
                for (int mt = 0; mt < 2; mt++) {
                    int r = 32 * wm + 16 * mt + g;
                    int qr = (r >> 1) & 3;
                    unsigned a0 = *(const unsigned*)&As[sp][r    ][(((2 * ks    ) ^ qr) << 2) + t];
                    unsigned a1 = *(const unsigned*)&As[sp][r + 8][(((2 * ks    ) ^ qr) << 2) + t];
                    unsigned a2 = *(const unsigned*)&As[sp][r    ][(((2 * ks + 1) ^ qr) << 2) + t];
                    unsigned a3 = *(const unsigned*)&As[sp][r + 8][(((2 * ks + 1) ^ qr) << 2) + t];
#pragma unroll
                    for (int nt = 0; nt < 4; nt++)
                        mma_f16(acc[mt][nt][0], acc[mt][nt][1], acc[mt][nt][2], acc[mt][nt][3],
                                a0, a1, a2, a3, bfr[nt][0], bfr[nt][1]);
                }
            }
        }
        __syncthreads();
    }

    // Q scale folds 1/sqrt(256) AND log2(e).
    const float scale = (mat == 0) ? 0.09014020181552054f : 1.0f;
#pragma unroll
    for (int mt = 0; mt < 2; mt++) {
        int r = m0 + 32 * wm + 16 * mt + g;
#pragma unroll
        for (int nt = 0; nt < 4; nt++) {
            int col = n0 + 32 * wn + 8 * nt + 2 * t;
            __half h00 = __float2half_rn(acc[mt][nt][0] * scale);
            __half h01 = __float2half_rn(acc[mt][nt][1] * scale);
            __half h10 = __float2half_rn(acc[mt][nt][2] * scale);
            __half h11 = __float2half_rn(acc[mt][nt][3] * scale);
            if (mat == 2) {
                g_Vt[(size_t)col * NTOK + r] = h00;
                g_Vt[(size_t)(col + 1) * NTOK + r] = h01;
                g_Vt[(size_t)col * NTOK + r + 8] = h10;
                g_Vt[(size_t)(col + 1) * NTOK + r + 8] = h11;
            } else {
                __half* dst = (mat == 0) ? g_Qh : g_Kh;
                *(__half2*)&dst[(size_t)r * DHEAD + col] = __halves2half2(h00, h01);
                *(__half2*)&dst[(size_t)(r + 8) * DHEAD + col] = __halves2half2(h10, h11);
            }
        }
    }
}

// ---------------- kernel 2: fp16 attention, 2 full barriers/iter ----------------
#define SMO_Q   0u        // [128][256] half, 16B-granule xor swizzle
#define SMO_K0  65536u
#define SMO_K1  98304u
#define SMO_V   131072u   // [256][64] half (V^T)
#define SMO_C   163840u   // 8 warp-private regions x 4KB
#define SMO_P   196608u   // [128] rows x 144B
#define SMO_L   215040u
#define SMEM_DYN (215040u + 1024u)

__global__ __launch_bounds__(256, 1) void attn_kernel(const float* __restrict__ cnt) {
    extern __shared__ char sm[];
    const uint32_t sb = smem_u32(sm);

    const int tid = threadIdx.x, w = tid >> 5, lane = tid & 31;
    const int g = lane >> 2, t = lane & 3;
    const int wm = w & 3, wh = w >> 2;
    const int m0 = blockIdx.x * BM;
    const int sp = blockIdx.y;
    const int jb0 = sp * (NTOK / NSPLIT);

    const int lr = lane & 7;
    const int lm = (lane >> 3) & 1;
    const int lh = lane >> 4;

    const int ar0 = 32 * wm + lr + 8 * lm;
    const uint32_t qb0 = sb + SMO_Q + (uint32_t)ar0 * 512u;
    const uint32_t qb1 = qb0 + 16u * 512u;
    const uint32_t pb0 = sb + SMO_P + (uint32_t)ar0 * 144u;
    const uint32_t pb1 = pb0 + 16u * 144u;
    const int bnr = lr + 8 * lh;
    const uint32_t kroff = (uint32_t)(32 * wh + bnr) * 512u;
    const uint32_t vb = sb + SMO_V + (uint32_t)(128 * wh + bnr) * 128u;

    const uint32_t cw = sb + SMO_C + (uint32_t)w * 4096u;
    const float* crow = &cnt[(size_t)(m0 + 32 * wm) * NTOK + 32 * wh];
    const int crr = lane >> 3;
    const int cf4 = lane & 7;

    // prologue: Q + K_0 as the initial "K group"
#pragma unroll
    for (int i = 0; i < 16; i++) {
        int e = tid + 256 * i;
        int r = e >> 5, blk = e & 31;
        uint32_t d = sb + SMO_Q + (uint32_t)r * 512u + (uint32_t)((blk ^ (r & 7)) << 4);
        cp16(d, &g_Qh[(size_t)(m0 + r) * DHEAD + 8 * blk]);
    }
#pragma unroll
    for (int i = 0; i < 8; i++) {
        int e = tid + 256 * i;
        int r = e >> 5, blk = e & 31;
        uint32_t d = sb + SMO_K0 + (uint32_t)r * 512u + (uint32_t)((blk ^ (r & 7)) << 4);
        cp16(d, &g_Kh[(size_t)(jb0 + r) * DHEAD + 8 * blk]);
    }
    CP_COMMIT();

    float O[2][16][4];
#pragma unroll
    for (int mt = 0; mt < 2; mt++)
#pragma unroll
        for (int nt = 0; nt < 16; nt++)
#pragma unroll
            for (int q = 0; q < 4; q++) O[mt][nt][q] = 0.f;
    float lA[2] = {0.f, 0.f}, lB[2] = {0.f, 0.f};

    for (int j = 0; j < JBLOCKS; j++) {
        const int jb = jb0 + j * BN;

        CP_WAIT(0);        // only K_j's group outstanding here
        __syncthreads();   // b1: K_j visible; all buffers free

        // ---- issue V_j + warp-private C_j (group G_V) ----
#pragma unroll
        for (int i = 0; i < 8; i++) {
            int e = tid + 256 * i;
            int dd = e >> 3, blk = e & 7;
            uint32_t d = sb + SMO_V + (uint32_t)dd * 128u + (uint32_t)((blk ^ (dd & 7)) << 4);
            cp16(d, &g_Vt[(size_t)dd * NTOK + jb + 8 * blk]);
        }
#pragma unroll
        for (int i = 0; i < 8; i++) {
            int row = crr + 4 * i;
            uint32_t d = cw + (uint32_t)row * 128u + (uint32_t)((cf4 ^ (row & 7)) << 4);
            cp16(d, crow + (size_t)row * NTOK + jb + 4 * cf4);
        }
        CP_COMMIT();

        // ---- issue K_{j+1} (group G_K; waited at next iter's top) ----
        if (j + 1 < JBLOCKS) {
            uint32_t kb = ((j + 1) & 1) ? SMO_K1 : SMO_K0;
#pragma unroll
            for (int i = 0; i < 8; i++) {
                int e = tid + 256 * i;
                int r = e >> 5, blk = e & 31;
                uint32_t d = sb + kb + (uint32_t)r * 512u + (uint32_t)((blk ^ (r & 7)) << 4);
                cp16(d, &g_Kh[(size_t)(jb + BN + r) * DHEAD + 8 * blk]);
            }
        }
        CP_COMMIT();

        // ---- QK_j ----
        const uint32_t kbuf = sb + ((j & 1) ? SMO_K1 : SMO_K0) + kroff;
        float S[2][4][4];
#pragma unroll
        for (int mt = 0; mt < 2; mt++)
#pragma unroll
            for (int nt = 0; nt < 4; nt++)
#pragma unroll
                for (int q = 0; q < 4; q++) S[mt][nt][q] = 0.f;

#pragma unroll
        for (int s = 0; s < 16; s++) {
            const uint32_t xa = (uint32_t)(((2 * s + lh) ^ lr) << 4);
            const uint32_t xb = (uint32_t)(((2 * s + lm) ^ lr) << 4);
            unsigned a0[4], a1[4], b0[4], b1[4];
            ldsm4(a0[0], a0[1], a0[2], a0[3], qb0 + xa);
            ldsm4(a1[0], a1[1], a1[2], a1[3], qb1 + xa);
            ldsm4(b0[0], b0[1], b0[2], b0[3], kbuf + xb);
            ldsm4(b1[0], b1[1], b1[2], b1[3], kbuf + 16u * 512u + xb);
            mma_f16(S[0][0][0], S[0][0][1], S[0][0][2], S[0][0][3], a0[0], a0[1], a0[2], a0[3], b0[0], b0[1]);
            mma_f16(S[0][1][0], S[0][1][1], S[0][1][2], S[0][1][3], a0[0], a0[1], a0[2], a0[3], b0[2], b0[3]);
            mma_f16(S[0][2][0], S[0][2][1], S[0][2][2], S[0][2][3], a0[0], a0[1], a0[2], a0[3], b1[0], b1[1]);
            mma_f16(S[0][3][0], S[0][3][1], S[0][3][2], S[0][3][3], a0[0], a0[1], a0[2], a0[3], b1[2], b1[3]);
            mma_f16(S[1][0][0], S[1][0][1], S[1][0][2], S[1][0][3], a1[0], a1[1], a1[2], a1[3], b0[0], b0[1]);
            mma_f16(S[1][1][0], S[1][1][1], S[1][1][2], S[1][1][3], a1[0], a1[1], a1[2], a1[3], b0[2], b0[3]);
            mma_f16(S[1][2][0], S[1][2][1], S[1][2][2], S[1][2][3], a1[0], a1[1], a1[2], a1[3], b1[0], b1[1]);
            mma_f16(S[1][3][0], S[1][3][1], S[1][3][2], S[1][3][3], a1[0], a1[1], a1[2], a1[3], b1[2], b1[3]);
        }

        // ---- epilogue, ungated ----
        CP_WAIT(1);
        __syncwarp();
        const char* Cw = sm + SMO_C + w * 4096;
        char* Ps = sm + SMO_P;
#pragma unroll
        for (int mt = 0; mt < 2; mt++) {
            int lrA = g + 16 * mt, lrB = lrA + 8;
            int rA = 32 * wm + lrA, rB = 32 * wm + lrB;
#pragma unroll
            for (int nt = 0; nt < 4; nt++) {
                int co = (((2 * nt + (t >> 1)) ^ g) << 4) + ((t & 1) << 3);
                float2 cA = *(const float2*)(Cw + lrA * 128 + co);
                float2 cB = *(const float2*)(Cw + lrB * 128 + co);
                float p0 = ex2f(S[mt][nt][0]) * cA.x;
                float p1 = ex2f(S[mt][nt][1]) * cA.y;
                float p2 = ex2f(S[mt][nt][2]) * cB.x;
                float p3 = ex2f(S[mt][nt][3]) * cB.y;
                lA[mt] += p0 + p1;          // per-thread partial; reduced once at end
                lB[mt] += p2 + p3;
                int q = (16 * wh + 4 * nt + t) << 2;
                *(__half2*)(Ps + rA * 144 + q) = __halves2half2(__float2half_rn(p0), __float2half_rn(p1));
                *(__half2*)(Ps + rB * 144 + q) = __halves2half2(__float2half_rn(p2), __float2half_rn(p3));
            }
        }
        __syncthreads();   // b2: P + V visible to all warps

        // ---- AV_j ----
#pragma unroll
        for (int s = 0; s < 4; s++) {
            const uint32_t xp = (uint32_t)((2 * s + lh) << 4);
            const uint32_t xv = (uint32_t)(((2 * s + lm) ^ lr) << 4);
            unsigned pa0[4], pa1[4];
            ldsm4(pa0[0], pa0[1], pa0[2], pa0[3], pb0 + xp);
            ldsm4(pa1[0], pa1[1], pa1[2], pa1[3], pb1 + xp);
#pragma unroll
            for (int p = 0; p < 8; p++) {
                unsigned vv[4];
                ldsm4(vv[0], vv[1], vv[2], vv[3], vb + (uint32_t)p * 2048u + xv);
                mma_f16(O[0][2 * p][0], O[0][2 * p][1], O[0][2 * p][2], O[0][2 * p][3],
                        pa0[0], pa0[1], pa0[2], pa0[3], vv[0], vv[1]);
                mma_f16(O[0][2 * p + 1][0], O[0][2 * p + 1][1], O[0][2 * p + 1][2], O[0][2 * p + 1][3],
                        pa0[0], pa0[1], pa0[2], pa0[3], vv[2], vv[3]);
                mma_f16(O[1][2 * p][0], O[1][2 * p][1], O[1][2 * p][2], O[1][2 * p][3],
                        pa1[0], pa1[1], pa1[2], pa1[3], vv[0], vv[1]);
                mma_f16(O[1][2 * p + 1][0], O[1][2 * p + 1][1], O[1][2 * p + 1][2], O[1][2 * p + 1][3],
                        pa1[0], pa1[1], pa1[2], pa1[3], vv[2], vv[3]);
            }
        }
    }

    // ---- final l reduction (once) ----
#pragma unroll
    for (int mt = 0; mt < 2; mt++) {
        lA[mt] += __shfl_xor_sync(0xffffffffu, lA[mt], 1);
        lA[mt] += __shfl_xor_sync(0xffffffffu, lA[mt], 2);
        lB[mt] += __shfl_xor_sync(0xffffffffu, lB[mt], 1);
        lB[mt] += __shfl_xor_sync(0xffffffffu, lB[mt], 2);
    }

    // ---- O writeout ----
    const int rA0 = 32 * wm + g, rB0 = rA0 + 8;
#pragma unroll
    for (int mt = 0; mt < 2; mt++) {
        int rA = m0 + rA0 + 16 * mt, rB = m0 + rB0 + 16 * mt;
#pragma unroll
        for (int nt = 0; nt < 16; nt++) {
            int col = 128 * wh + 8 * nt + 2 * t;
            *(float2*)&g_Op[sp][rA][col] = make_float2(O[mt][nt][0], O[mt][nt][1]);
            *(float2*)&g_Op[sp][rB][col] = make_float2(O[mt][nt][2], O[mt][nt][3]);
        }
    }

    float* Lr = (float*)(sm + SMO_L);
    if (t == 0) {
#pragma unroll
        for (int mt = 0; mt < 2; mt++) {
            Lr[wh * 128 + rA0 + 16 * mt] = lA[mt];
            Lr[wh * 128 + rB0 + 16 * mt] = lB[mt];
        }
    }
    __syncthreads();
    if (tid < 128) g_ls[sp][m0 + tid] = Lr[tid] + Lr[128 + tid];
}

// ---------------- kernel 3: combine + ELU (float4, grid 2048) ----------------
__global__ __launch_bounds__(256) void combine_kernel(float* __restrict__ out) {
    const int idx = blockIdx.x * 256 + threadIdx.x;     // 524288 threads
    const int row = idx >> 6;
    const int d4 = (idx & 63) << 2;
    float4 a = *(const float4*)&g_Op[0][row][d4];
    float4 b = *(const float4*)&g_Op[1][row][d4];
    float inv = 1.0f / (g_ls[0][row] + g_ls[1][row]);
    float r0 = (a.x + b.x) * inv, r1 = (a.y + b.y) * inv;
    float r2 = (a.z + b.z) * inv, r3 = (a.w + b.w) * inv;
    float4 o;
    o.x = (r0 > 0.f) ? r0 : expm1f(r0);
    o.y = (r1 > 0.f) ? r1 : expm1f(r1);
    o.z = (r2 > 0.f) ? r2 : expm1f(r2);
    o.w = (r3 > 0.f) ? r3 : expm1f(r3);
    *(float4*)&out[(size_t)row * DHEAD + d4] = o;
}

// ---------------- launch ----------------
extern "C" void kernel_launch(void* const* d_in, const int* in_sizes, int n_in,
                              void* d_out, int out_size) {
    (void)in_sizes; (void)n_in; (void)out_size;
    const float* feat = (const float*)d_in[0];
    const float* cnt = (const float*)d_in[1];
    const float* Wq = (const float*)d_in[2];
    const float* Wk = (const float*)d_in[3];
    const float* Wv = (const float*)d_in[4];

    prep_w<<<(3 * (DIN / 2) * DHEAD + 255) / 256, 256>>>(Wq, Wk, Wv);

    proj_kernel<<<dim3(NTOK / 64, DHEAD / 128, 3), 256>>>(feat);

    cudaFuncSetAttribute(attn_kernel, cudaFuncAttributeMaxDynamicSharedMemorySize, (int)SMEM_DYN);
    attn_kernel<<<dim3(NTOK / BM, NSPLIT), 256, SMEM_DYN>>>(cnt);

    combine_kernel<<<NTOK * DHEAD / 1024, 256>>>((float*)d_out);
}

// round 16
// speedup vs baseline: 1.3301x; 1.1147x over previous
#include <cuda_runtime.h>
#include <cuda_fp16.h>
#include <cstdint>

#define NTOK 8192
#define DIN  512
#define DHEAD 256
#define BM 128
#define BN 64
#define GRID_ATTN 152          // GB300 SM count
#define NUNITS 8192            // 64 tiles * 128 j-blocks
#define MAXP 4                 // max CTAs overlapping one tile (53-unit segments)

// ---------------- scratch ----------------
__device__ __half2 g_Wp[3 * (DIN / 2) * DHEAD];  // W packed as k-pairs, fp16
__device__ __half  g_Qh[NTOK * DHEAD];        // fp16, pre-scaled by log2e/16
__device__ __half  g_Kh[NTOK * DHEAD];        // fp16
__device__ __half  g_Vt[DHEAD * NTOK];        // V transposed [d][tok], fp16
__device__ float   g_Opn[MAXP][NTOK][DHEAD];  // up to 4 partials per tile
__device__ float   g_lsn[MAXP][NTOK];

// ---------------- helpers ----------------
__device__ __forceinline__ uint32_t smem_u32(const void* p) {
    uint32_t a;
    asm("{ .reg .u64 t; cvta.to.shared.u64 t, %1; cvt.u32.u64 %0, t; }" : "=r"(a) : "l"(p));
    return a;
}
__device__ __forceinline__ void cp16(uint32_t dst, const void* src) {
    asm volatile("cp.async.cg.shared.global [%0], [%1], 16;" :: "r"(dst), "l"(src));
}
#define CP_COMMIT() asm volatile("cp.async.commit_group;" ::: "memory")
#define CP_WAIT(n)  asm volatile("cp.async.wait_group %0;" :: "n"(n) : "memory")

__device__ __forceinline__ void ldsm4(unsigned& r0, unsigned& r1, unsigned& r2, unsigned& r3,
                                      uint32_t a) {
    asm volatile("ldmatrix.sync.aligned.m8n8.x4.shared.b16 {%0,%1,%2,%3}, [%4];"
                 : "=r"(r0), "=r"(r1), "=r"(r2), "=r"(r3) : "r"(a));
}

__device__ __forceinline__ void mma_f16(float& c0, float& c1, float& c2, float& c3,
                                        unsigned a0, unsigned a1, unsigned a2, unsigned a3,
                                        unsigned b0, unsigned b1) {
    asm volatile(
        "mma.sync.aligned.m16n8k16.row.col.f32.f16.f16.f32 "
        "{%0,%1,%2,%3}, {%4,%5,%6,%7}, {%8,%9}, {%0,%1,%2,%3};"
        : "+f"(c0), "+f"(c1), "+f"(c2), "+f"(c3)
        : "r"(a0), "r"(a1), "r"(a2), "r"(a3), "r"(b0), "r"(b1));
}

__device__ __forceinline__ float ex2f(float x) {
    float r; asm("ex2.approx.f32 %0, %1;" : "=f"(r) : "f"(x)); return r;
}

__device__ __forceinline__ unsigned pack_hi(float a, float b) {
    __half2 h = __halves2half2(__float2half_rn(a), __float2half_rn(b));
    return *(unsigned*)&h;
}
__device__ __forceinline__ unsigned pack_lo(float a, float b) {
    float ra = a - __half2float(__float2half_rn(a));
    float rb = b - __half2float(__float2half_rn(b));
    __half2 h = __halves2half2(__float2half_rn(ra), __float2half_rn(rb));
    return *(unsigned*)&h;
}

// ---------------- kernel 0: pack W (1.5 MB one-time) ----------------
__global__ __launch_bounds__(256) void prep_w(const float* __restrict__ Wq,
                                              const float* __restrict__ Wk,
                                              const float* __restrict__ Wv) {
    const int j = blockIdx.x * 256 + threadIdx.x;
    const int WSZ = (DIN / 2) * DHEAD;
    if (j < 3 * WSZ) {
        int mat = j / WSZ;
        int r = j - mat * WSZ;
        int k2 = r / DHEAD, n = r % DHEAD;
        const float* __restrict__ W = (mat == 0) ? Wq : ((mat == 1) ? Wk : Wv);
        g_Wp[j] = __halves2half2(__float2half_rn(W[(size_t)(2 * k2) * DHEAD + n]),
                                 __float2half_rn(W[(size_t)(2 * k2 + 1) * DHEAD + n]));
    }
}

// ---------------- kernel 1: QKV projection — BM=64, BN=128, 32x32 warp tiles ----------------
__global__ __launch_bounds__(256) void proj_kernel(const float* __restrict__ feat) {
    __shared__ __align__(16) __half2 As[2][64][16];
    __shared__ __align__(16) __half2 Bs[128][16];

    const int tid = threadIdx.x;
    const int w = tid >> 5, lane = tid & 31, g = lane >> 2, t = lane & 3;
    const int wm = w >> 2;
    const int wn = w & 3;
    const int m0 = blockIdx.x * 64;
    const int n0 = blockIdx.y * 128;
    const int mat = blockIdx.z;
    const __half2* __restrict__ Wp = &g_Wp[mat * (DIN / 2) * DHEAD];

    const int ar = tid >> 2;
    const int ac = tid & 3;
    const int aq = (ar >> 1) & 3;
    const int bn = tid & 127;
    const int bcb = (tid >> 7) << 1;
    const int bq = (bn >> 1) & 3;

    float4 aR[2];
    unsigned bR[8];
    {
        const float* ap = &feat[(size_t)(m0 + ar) * DIN + ac * 8];
        aR[0] = *(const float4*)(ap);
        aR[1] = *(const float4*)(ap + 4);
        const __half2* bp = &Wp[(size_t)(bcb * 4) * DHEAD + n0 + bn];
#pragma unroll
        for (int jj = 0; jj < 8; jj++) bR[jj] = *(const unsigned*)&bp[(size_t)jj * DHEAD];
    }

    float acc[2][4][4];
#pragma unroll
    for (int mt = 0; mt < 2; mt++)
#pragma unroll
        for (int nt = 0; nt < 4; nt++)
#pragma unroll
            for (int q = 0; q < 4; q++) acc[mt][nt][q] = 0.f;

    for (int it = 0; it < 16; it++) {
        {
            uint4 hq, lq;
            hq.x = pack_hi(aR[0].x, aR[0].y); hq.y = pack_hi(aR[0].z, aR[0].w);
            hq.z = pack_hi(aR[1].x, aR[1].y); hq.w = pack_hi(aR[1].z, aR[1].w);
            lq.x = pack_lo(aR[0].x, aR[0].y); lq.y = pack_lo(aR[0].z, aR[0].w);
            lq.z = pack_lo(aR[1].x, aR[1].y); lq.w = pack_lo(aR[1].z, aR[1].w);
            *(uint4*)&As[0][ar][(ac ^ aq) << 2] = hq;
            *(uint4*)&As[1][ar][(ac ^ aq) << 2] = lq;
            uint4 bq0, bq1;
            bq0.x = bR[0]; bq0.y = bR[1]; bq0.z = bR[2]; bq0.w = bR[3];
            bq1.x = bR[4]; bq1.y = bR[5]; bq1.z = bR[6]; bq1.w = bR[7];
            *(uint4*)&Bs[bn][((bcb    ) ^ bq) << 2] = bq0;
            *(uint4*)&Bs[bn][((bcb + 1) ^ bq) << 2] = bq1;
        }
        __syncthreads();

        if (it + 1 < 16) {
            const int kb = (it + 1) << 5;
            const float* ap = &feat[(size_t)(m0 + ar) * DIN + kb + ac * 8];
            aR[0] = *(const float4*)(ap);
            aR[1] = *(const float4*)(ap + 4);
            const __half2* bp = &Wp[(size_t)(kb / 2 + bcb * 4) * DHEAD + n0 + bn];
#pragma unroll
            for (int jj = 0; jj < 8; jj++) bR[jj] = *(const unsigned*)&bp[(size_t)jj * DHEAD];
        }

#pragma unroll
        for (int ks = 0; ks < 2; ks++) {
            unsigned bfr[4][2];
#pragma unroll
            for (int nt = 0; nt < 4; nt++) {
                int n = 32 * wn + 8 * nt + g;
                int qn = (n >> 1) & 3;
                bfr[nt][0] = *(const unsigned*)&Bs[n][(((2 * ks    ) ^ qn) << 2) + t];
                bfr[nt][1] = *(const unsigned*)&Bs[n][(((2 * ks + 1) ^ qn) << 2) + t];
            }
#pragma unroll
            for (int sp = 0; sp < 2; sp++) {
#pragma unroll
                for (int mt = 0; mt < 2; mt++) {
                    int r = 32 * wm + 16 * mt + g;
                    int qr = (r >> 1) & 3;
                    unsigned a0 = *(const unsigned*)&As[sp][r    ][(((2 * ks    ) ^ qr) << 2) + t];
                    unsigned a1 = *(const unsigned*)&As[sp][r + 8][(((2 * ks    ) ^ qr) << 2) + t];
                    unsigned a2 = *(const unsigned*)&As[sp][r    ][(((2 * ks + 1) ^ qr) << 2) + t];
                    unsigned a3 = *(const unsigned*)&As[sp][r + 8][(((2 * ks + 1) ^ qr) << 2) + t];
#pragma unroll
                    for (int nt = 0; nt < 4; nt++)
                        mma_f16(acc[mt][nt][0], acc[mt][nt][1], acc[mt][nt][2], acc[mt][nt][3],
                                a0, a1, a2, a3, bfr[nt][0], bfr[nt][1]);
                }
            }
        }
        __syncthreads();
    }

    // Q scale folds 1/sqrt(256) AND log2(e).
    const float scale = (mat == 0) ? 0.09014020181552054f : 1.0f;
#pragma unroll
    for (int mt = 0; mt < 2; mt++) {
        int r = m0 + 32 * wm + 16 * mt + g;
#pragma unroll
        for (int nt = 0; nt < 4; nt++) {
            int col = n0 + 32 * wn + 8 * nt + 2 * t;
            __half h00 = __float2half_rn(acc[mt][nt][0] * scale);
            __half h01 = __float2half_rn(acc[mt][nt][1] * scale);
            __half h10 = __float2half_rn(acc[mt][nt][2] * scale);
            __half h11 = __float2half_rn(acc[mt][nt][3] * scale);
            if (mat == 2) {
                g_Vt[(size_t)col * NTOK + r] = h00;
                g_Vt[(size_t)(col + 1) * NTOK + r] = h01;
                g_Vt[(size_t)col * NTOK + r + 8] = h10;
                g_Vt[(size_t)(col + 1) * NTOK + r + 8] = h11;
            } else {
                __half* dst = (mat == 0) ? g_Qh : g_Kh;
                *(__half2*)&dst[(size_t)r * DHEAD + col] = __halves2half2(h00, h01);
                *(__half2*)&dst[(size_t)(r + 8) * DHEAD + col] = __halves2half2(h10, h11);
            }
        }
    }
}

// ---------------- kernel 2: fp16 attention, 152-CTA balanced static partition ----------------
#define SMO_Q   0u        // [128][256] half, 16B-granule xor swizzle
#define SMO_K0  65536u
#define SMO_K1  98304u
#define SMO_V   131072u   // [256][64] half (V^T)
#define SMO_C   163840u   // 8 warp-private regions x 4KB
#define SMO_P   196608u   // [128] rows x 144B
#define SMO_L   215040u
#define SMEM_DYN (215040u + 1024u)

__global__ __launch_bounds__(256, 1) void attn_kernel(const float* __restrict__ cnt) {
    extern __shared__ char sm[];
    const uint32_t sb = smem_u32(sm);

    const int tid = threadIdx.x, w = tid >> 5, lane = tid & 31;
    const int g = lane >> 2, t = lane & 3;
    const int wm = w & 3, wh = w >> 2;

    const int lr = lane & 7;
    const int lm = (lane >> 3) & 1;
    const int lh = lane >> 4;

    const int ar0 = 32 * wm + lr + 8 * lm;
    const uint32_t qb0 = sb + SMO_Q + (uint32_t)ar0 * 512u;
    const uint32_t qb1 = qb0 + 16u * 512u;
    const uint32_t pb0 = sb + SMO_P + (uint32_t)ar0 * 144u;
    const uint32_t pb1 = pb0 + 16u * 144u;
    const int bnr = lr + 8 * lh;
    const uint32_t kroff = (uint32_t)(32 * wh + bnr) * 512u;
    const uint32_t vb = sb + SMO_V + (uint32_t)(128 * wh + bnr) * 128u;
    const uint32_t cw = sb + SMO_C + (uint32_t)w * 4096u;
    const int crr = lane >> 3;
    const int cf4 = lane & 7;
    const int rA0 = 32 * wm + g, rB0 = rA0 + 8;
    float* Lr = (float*)(sm + SMO_L);

    // ---- static partition of 8192 j-block units over 152 CTAs ----
    const int c = blockIdx.x;
    const int u0 = (c * NUNITS) / GRID_ATTN;
    const int u1 = ((c + 1) * NUNITS) / GRID_ATTN;

    int seg = u0;
    while (seg < u1) {
        const int tile = seg >> 7;                       // 128 blocks per tile
        const int send = min(u1, (tile + 1) << 7);
        const int nb = send - seg;
        const int m0 = tile * BM;
        // first CTA covering this tile = CTA covering unit tile*128
        const int cfirst = (((tile << 7) + 1) * GRID_ATTN - 1) >> 13;
        const int slot = c - cfirst;                     // 0..MAXP-1

        const float* crow = &cnt[(size_t)(m0 + 32 * wm) * NTOK + 32 * wh];

        // ---- segment prologue: Q tile + first K block (one group) ----
#pragma unroll
        for (int i = 0; i < 16; i++) {
            int e = tid + 256 * i;
            int r = e >> 5, blk = e & 31;
            uint32_t d = sb + SMO_Q + (uint32_t)r * 512u + (uint32_t)((blk ^ (r & 7)) << 4);
            cp16(d, &g_Qh[(size_t)(m0 + r) * DHEAD + 8 * blk]);
        }
        {
            const int jb = (seg - (tile << 7)) * BN;
#pragma unroll
            for (int i = 0; i < 8; i++) {
                int e = tid + 256 * i;
                int r = e >> 5, blk = e & 31;
                uint32_t d = sb + SMO_K0 + (uint32_t)r * 512u + (uint32_t)((blk ^ (r & 7)) << 4);
                cp16(d, &g_Kh[(size_t)(jb + r) * DHEAD + 8 * blk]);
            }
        }
        CP_COMMIT();

        float O[2][16][4];
#pragma unroll
        for (int mt = 0; mt < 2; mt++)
#pragma unroll
            for (int nt = 0; nt < 16; nt++)
#pragma unroll
                for (int q = 0; q < 4; q++) O[mt][nt][q] = 0.f;
        float lA[2] = {0.f, 0.f}, lB[2] = {0.f, 0.f};

        for (int bi = 0; bi < nb; bi++) {
            const int jb = (seg - (tile << 7) + bi) * BN;

            CP_WAIT(0);        // only K_bi's group outstanding here
            __syncthreads();   // b1: K_bi visible; all buffers free

            // ---- issue V + warp-private C (group G_V) ----
#pragma unroll
            for (int i = 0; i < 8; i++) {
                int e = tid + 256 * i;
                int dd = e >> 3, blk = e & 7;
                uint32_t d = sb + SMO_V + (uint32_t)dd * 128u + (uint32_t)((blk ^ (dd & 7)) << 4);
                cp16(d, &g_Vt[(size_t)dd * NTOK + jb + 8 * blk]);
            }
#pragma unroll
            for (int i = 0; i < 8; i++) {
                int row = crr + 4 * i;
                uint32_t d = cw + (uint32_t)row * 128u + (uint32_t)((cf4 ^ (row & 7)) << 4);
                cp16(d, crow + (size_t)row * NTOK + jb + 4 * cf4);
            }
            CP_COMMIT();

            // ---- issue K_{bi+1} ----
            if (bi + 1 < nb) {
                uint32_t kb = ((bi + 1) & 1) ? SMO_K1 : SMO_K0;
#pragma unroll
                for (int i = 0; i < 8; i++) {
                    int e = tid + 256 * i;
                    int r = e >> 5, blk = e & 31;
                    uint32_t d = sb + kb + (uint32_t)r * 512u + (uint32_t)((blk ^ (r & 7)) << 4);
                    cp16(d, &g_Kh[(size_t)(jb + BN + r) * DHEAD + 8 * blk]);
                }
            }
            CP_COMMIT();

            // ---- QK ----
            const uint32_t kbuf = sb + ((bi & 1) ? SMO_K1 : SMO_K0) + kroff;
            float S[2][4][4];
#pragma unroll
            for (int mt = 0; mt < 2; mt++)
#pragma unroll
                for (int nt = 0; nt < 4; nt++)
#pragma unroll
                    for (int q = 0; q < 4; q++) S[mt][nt][q] = 0.f;

#pragma unroll
            for (int s = 0; s < 16; s++) {
                const uint32_t xa = (uint32_t)(((2 * s + lh) ^ lr) << 4);
                const uint32_t xb = (uint32_t)(((2 * s + lm) ^ lr) << 4);
                unsigned a0[4], a1[4], b0[4], b1[4];
                ldsm4(a0[0], a0[1], a0[2], a0[3], qb0 + xa);
                ldsm4(a1[0], a1[1], a1[2], a1[3], qb1 + xa);
                ldsm4(b0[0], b0[1], b0[2], b0[3], kbuf + xb);
                ldsm4(b1[0], b1[1], b1[2], b1[3], kbuf + 16u * 512u + xb);
                mma_f16(S[0][0][0], S[0][0][1], S[0][0][2], S[0][0][3], a0[0], a0[1], a0[2], a0[3], b0[0], b0[1]);
                mma_f16(S[0][1][0], S[0][1][1], S[0][1][2], S[0][1][3], a0[0], a0[1], a0[2], a0[3], b0[2], b0[3]);
                mma_f16(S[0][2][0], S[0][2][1], S[0][2][2], S[0][2][3], a0[0], a0[1], a0[2], a0[3], b1[0], b1[1]);
                mma_f16(S[0][3][0], S[0][3][1], S[0][3][2], S[0][3][3], a0[0], a0[1], a0[2], a0[3], b1[2], b1[3]);
                mma_f16(S[1][0][0], S[1][0][1], S[1][0][2], S[1][0][3], a1[0], a1[1], a1[2], a1[3], b0[0], b0[1]);
                mma_f16(S[1][1][0], S[1][1][1], S[1][1][2], S[1][1][3], a1[0], a1[1], a1[2], a1[3], b0[2], b0[3]);
                mma_f16(S[1][2][0], S[1][2][1], S[1][2][2], S[1][2][3], a1[0], a1[1], a1[2], a1[3], b1[0], b1[1]);
                mma_f16(S[1][3][0], S[1][3][1], S[1][3][2], S[1][3][3], a1[0], a1[1], a1[2], a1[3], b1[2], b1[3]);
            }

            // ---- epilogue, ungated ----
            CP_WAIT(1);
            __syncwarp();
            const char* Cw = sm + SMO_C + w * 4096;
            char* Ps = sm + SMO_P;
#pragma unroll
            for (int mt = 0; mt < 2; mt++) {
                int lrA = g + 16 * mt, lrB = lrA + 8;
                int rA = 32 * wm + lrA, rB = 32 * wm + lrB;
#pragma unroll
                for (int nt = 0; nt < 4; nt++) {
                    int co = (((2 * nt + (t >> 1)) ^ g) << 4) + ((t & 1) << 3);
                    float2 cA = *(const float2*)(Cw + lrA * 128 + co);
                    float2 cB = *(const float2*)(Cw + lrB * 128 + co);
                    float p0 = ex2f(S[mt][nt][0]) * cA.x;
                    float p1 = ex2f(S[mt][nt][1]) * cA.y;
                    float p2 = ex2f(S[mt][nt][2]) * cB.x;
                    float p3 = ex2f(S[mt][nt][3]) * cB.y;
                    lA[mt] += p0 + p1;
                    lB[mt] += p2 + p3;
                    int q = (16 * wh + 4 * nt + t) << 2;
                    *(__half2*)(Ps + rA * 144 + q) = __halves2half2(__float2half_rn(p0), __float2half_rn(p1));
                    *(__half2*)(Ps + rB * 144 + q) = __halves2half2(__float2half_rn(p2), __float2half_rn(p3));
                }
            }
            __syncthreads();   // b2: P + V visible to all warps

            // ---- AV ----
#pragma unroll
            for (int s = 0; s < 4; s++) {
                const uint32_t xp = (uint32_t)((2 * s + lh) << 4);
                const uint32_t xv = (uint32_t)(((2 * s + lm) ^ lr) << 4);
                unsigned pa0[4], pa1[4];
                ldsm4(pa0[0], pa0[1], pa0[2], pa0[3], pb0 + xp);
                ldsm4(pa1[0], pa1[1], pa1[2], pa1[3], pb1 + xp);
#pragma unroll
                for (int p = 0; p < 8; p++) {
                    unsigned vv[4];
                    ldsm4(vv[0], vv[1], vv[2], vv[3], vb + (uint32_t)p * 2048u + xv);
                    mma_f16(O[0][2 * p][0], O[0][2 * p][1], O[0][2 * p][2], O[0][2 * p][3],
                            pa0[0], pa0[1], pa0[2], pa0[3], vv[0], vv[1]);
                    mma_f16(O[0][2 * p + 1][0], O[0][2 * p + 1][1], O[0][2 * p + 1][2], O[0][2 * p + 1][3],
                            pa0[0], pa0[1], pa0[2], pa0[3], vv[2], vv[3]);
                    mma_f16(O[1][2 * p][0], O[1][2 * p][1], O[1][2 * p][2], O[1][2 * p][3],
                            pa1[0], pa1[1], pa1[2], pa1[3], vv[0], vv[1]);
                    mma_f16(O[1][2 * p + 1][0], O[1][2 * p + 1][1], O[1][2 * p + 1][2], O[1][2 * p + 1][3],
                            pa1[0], pa1[1], pa1[2], pa1[3], vv[2], vv[3]);
                }
            }
        }

        // ---- per-segment: reduce l, write partials into this CTA's slot ----
#pragma unroll
        for (int mt = 0; mt < 2; mt++) {
            lA[mt] += __shfl_xor_sync(0xffffffffu, lA[mt], 1);
            lA[mt] += __shfl_xor_sync(0xffffffffu, lA[mt], 2);
            lB[mt] += __shfl_xor_sync(0xffffffffu, lB[mt], 1);
            lB[mt] += __shfl_xor_sync(0xffffffffu, lB[mt], 2);
        }
#pragma unroll
        for (int mt = 0; mt < 2; mt++) {
            int rA = m0 + rA0 + 16 * mt, rB = m0 + rB0 + 16 * mt;
#pragma unroll
            for (int nt = 0; nt < 16; nt++) {
                int col = 128 * wh + 8 * nt + 2 * t;
                *(float2*)&g_Opn[slot][rA][col] = make_float2(O[mt][nt][0], O[mt][nt][1]);
                *(float2*)&g_Opn[slot][rB][col] = make_float2(O[mt][nt][2], O[mt][nt][3]);
            }
        }
        if (t == 0) {
#pragma unroll
            for (int mt = 0; mt < 2; mt++) {
                Lr[wh * 128 + rA0 + 16 * mt] = lA[mt];
                Lr[wh * 128 + rB0 + 16 * mt] = lB[mt];
            }
        }
        __syncthreads();
        if (tid < 128) g_lsn[slot][m0 + tid] = Lr[tid] + Lr[128 + tid];
        __syncthreads();   // Lr free before next segment

        seg = send;
    }
}

// ---------------- kernel 3: combine np partials + ELU (float4) ----------------
__global__ __launch_bounds__(256) void combine_kernel(float* __restrict__ out) {
    const int idx = blockIdx.x * 256 + threadIdx.x;     // 524288 threads
    const int row = idx >> 6;
    const int d4 = (idx & 63) << 2;
    const int tile = row >> 7;
    const int cfirst = (((tile << 7) + 1) * GRID_ATTN - 1) >> 13;
    const int clast  = (((tile << 7) + 128) * GRID_ATTN - 1) >> 13;
    const int np = clast - cfirst + 1;                  // 2..4

    float den = 0.f, nx = 0.f, ny = 0.f, nz = 0.f, nw = 0.f;
#pragma unroll 4
    for (int s = 0; s < np; s++) {
        float4 a = *(const float4*)&g_Opn[s][row][d4];
        den += g_lsn[s][row];
        nx += a.x; ny += a.y; nz += a.z; nw += a.w;
    }
    float inv = 1.0f / den;
    float r0 = nx * inv, r1 = ny * inv, r2 = nz * inv, r3 = nw * inv;
    float4 o;
    o.x = (r0 > 0.f) ? r0 : expm1f(r0);
    o.y = (r1 > 0.f) ? r1 : expm1f(r1);
    o.z = (r2 > 0.f) ? r2 : expm1f(r2);
    o.w = (r3 > 0.f) ? r3 : expm1f(r3);
    *(float4*)&out[(size_t)row * DHEAD + d4] = o;
}

// ---------------- launch ----------------
extern "C" void kernel_launch(void* const* d_in, const int* in_sizes, int n_in,
                              void* d_out, int out_size) {
    (void)in_sizes; (void)n_in; (void)out_size;
    const float* feat = (const float*)d_in[0];
    const float* cnt = (const float*)d_in[1];
    const float* Wq = (const float*)d_in[2];
    const float* Wk = (const float*)d_in[3];
    const float* Wv = (const float*)d_in[4];

    prep_w<<<(3 * (DIN / 2) * DHEAD + 255) / 256, 256>>>(Wq, Wk, Wv);

    proj_kernel<<<dim3(NTOK / 64, DHEAD / 128, 3), 256>>>(feat);

    cudaFuncSetAttribute(attn_kernel, cudaFuncAttributeMaxDynamicSharedMemorySize, (int)SMEM_DYN);
    attn_kernel<<<GRID_ATTN, 256, SMEM_DYN>>>(cnt);

    combine_kernel<<<NTOK * DHEAD / 1024, 256>>>((float*)d_out);
}